// round 6
// baseline (speedup 1.0000x reference)
#include <cuda_runtime.h>
#include <math.h>

// Problem constants (B=2, T=16, N=1024, D=3)
#define BT       32
#define NPTS     1024
#define TPB      128
#define NQ       16                   // candidate lane-split groups
#define POWN     8                    // owned points per thread
#define OGRP     (TPB / NQ)           // 8 owned groups
#define OWNED    (OGRP * POWN)        // 64 owned points per block
#define OCH      (NPTS / OWNED)       // 16 owned chunks per (batch, direction)
#define CPAIRS   (NPTS / 2)           // 512 packed candidate pairs in smem
#define ITERS    (CPAIRS / NQ)        // 32 pair-iterations per thread
#define NBLOCKS  (BT * 2 * OCH)       // 1024
#define EPS      1e-6f

__device__ float        g_partials[NBLOCKS];
__device__ unsigned int g_count = 0;

// ---- packed f32x2 helpers (sm_100+; ptxas never auto-fuses) ----
__device__ __forceinline__ unsigned long long pack2(float a, float b) {
    unsigned long long r;
    asm("mov.b64 %0, {%1, %2};" : "=l"(r) : "f"(a), "f"(b));
    return r;
}
__device__ __forceinline__ unsigned long long fma2(unsigned long long a,
                                                   unsigned long long b,
                                                   unsigned long long c) {
    unsigned long long d;
    asm("fma.rn.f32x2 %0, %1, %2, %3;" : "=l"(d) : "l"(a), "l"(b), "l"(c));
    return d;
}
__device__ __forceinline__ void unpack2(unsigned long long v, float& lo, float& hi) {
    asm("mov.b64 {%0, %1}, %2;" : "=f"(lo), "=f"(hi) : "l"(v));
}

__global__ void __launch_bounds__(TPB, 4)
chamfer_kernel(const float* __restrict__ x, const float* __restrict__ y,
               float* __restrict__ out) {
    // Candidate pairs: 32B = {x0,x1, y0,y1, z0,z1, -h0,-h1}; 512 pairs = 16KB
    __shared__ float s_c[CPAIRS * 8];
    __shared__ float s_own[OWNED * 3];          // raw owned coords (768B)
    __shared__ float warp_sums[TPB / 32];
    __shared__ bool  sh_last;

    const int bt    = blockIdx.x >> 5;          // batch (32)
    const int dir   = (blockIdx.x >> 4) & 1;    // 0: owned=x, cand=y; 1: reverse
    const int chunk = blockIdx.x & 15;          // owned chunk (16)
    const int tid   = threadIdx.x;

    const float* xb = x + (size_t)bt * NPTS * 3;
    const float* yb = y + (size_t)bt * NPTS * 3;
    const float* ownp = dir ? yb : xb;
    const float* cndp = dir ? xb : yb;

    // ---- stage owned chunk raw via coalesced float4 (64 pts = 48 float4) ----
    if (tid < OWNED * 3 / 4) {
        const float4 v = ((const float4*)(ownp + (size_t)chunk * OWNED * 3))[tid];
        ((float4*)s_own)[tid] = v;
    }

    // ---- stage ALL 1024 candidates, coalesced float4 + register repack ----
    {
        // thread t handles pairs 4t..4t+3 (points 8t..8t+7, floats 24t..24t+23)
        const float4* cf = (const float4*)cndp;
        float L[24];
#pragma unroll
        for (int j = 0; j < 6; ++j) {
            float4 v = cf[6 * tid + j];
            L[4 * j + 0] = v.x; L[4 * j + 1] = v.y;
            L[4 * j + 2] = v.z; L[4 * j + 3] = v.w;
        }
#pragma unroll
        for (int r = 0; r < 4; ++r) {           // local pair r
            float x0 = L[6 * r + 0], y0 = L[6 * r + 1], z0 = L[6 * r + 2];
            float x1 = L[6 * r + 3], y1 = L[6 * r + 4], z1 = L[6 * r + 5];
            float nh0 = -0.5f * (x0 * x0 + y0 * y0 + z0 * z0);
            float nh1 = -0.5f * (x1 * x1 + y1 * y1 + z1 * z1);
            float* dst = s_c + (4 * tid + r) * 8;
            ((float4*)dst)[0] = make_float4(x0, x1, y0, y1);
            ((float4*)dst)[1] = make_float4(z0, z1, nh0, nh1);
        }
    }
    __syncthreads();

    // ---- owned register tile: 8 points from smem, splatted for f32x2 ----
    const int q = tid & (NQ - 1);               // candidate group 0..15
    const int g = tid >> 4;                     // owned group 0..7
    unsigned long long Ax2[POWN], Ay2[POWN], Az2[POWN];
    float h[POWN];
#pragma unroll
    for (int k = 0; k < POWN; ++k) {
        const int o = g + OGRP * k;             // local owned index
        float a0 = s_own[3 * o + 0], a1 = s_own[3 * o + 1], a2 = s_own[3 * o + 2];
        Ax2[k] = pack2(a0, a0);
        Ay2[k] = pack2(a1, a1);
        Az2[k] = pack2(a2, a2);
        h[k]   = 0.5f * (a0 * a0 + a1 * a1 + a2 * a2);
    }

    float mlo[POWN], mhi[POWN];
#pragma unroll
    for (int k = 0; k < POWN; ++k) { mlo[k] = -INFINITY; mhi[k] = -INFINITY; }

    // ---- hot loop: one 32B candidate-pair load feeds 8 owned points ----
    const ulonglong2* cp = (const ulonglong2*)s_c;
#pragma unroll 8
    for (int i = 0; i < ITERS; ++i) {
        const int pr = NQ * i + q;
        ulonglong2 va = cp[2 * pr];             // (x0,x1),(y0,y1)
        ulonglong2 vb = cp[2 * pr + 1];         // (z0,z1),(-h0,-h1)
#pragma unroll
        for (int k = 0; k < POWN; ++k) {
            unsigned long long t = fma2(Az2[k], vb.x, vb.y);
            t = fma2(Ay2[k], va.y, t);
            t = fma2(Ax2[k], va.x, t);
            float lo, hi;
            unpack2(t, lo, hi);
            mlo[k] = fmaxf(mlo[k], lo);
            mhi[k] = fmaxf(mhi[k], hi);
        }
    }

    // ---- combine the 16 candidate groups (within warp; g preserved) ----
    float contrib = 0.0f;
#pragma unroll
    for (int k = 0; k < POWN; ++k) {
        float m = fmaxf(mlo[k], mhi[k]);
        m = fmaxf(m, __shfl_xor_sync(0xFFFFFFFFu, m, 1));
        m = fmaxf(m, __shfl_xor_sync(0xFFFFFFFFu, m, 2));
        m = fmaxf(m, __shfl_xor_sync(0xFFFFFFFFu, m, 4));
        m = fmaxf(m, __shfl_xor_sync(0xFFFFFFFFu, m, 8));
        // min_i sq = 2*(h - m); clamp, dist = sqrt(EPS + sq)
        float sq = fmaxf(2.0f * (h[k] - m), 0.0f);
        if (q == 0) contrib += sqrtf(EPS + sq);
    }

    // ---- block reduction (fixed order -> deterministic) ----
#pragma unroll
    for (int off = 16; off > 0; off >>= 1)
        contrib += __shfl_down_sync(0xFFFFFFFFu, contrib, off);
    if ((tid & 31) == 0) warp_sums[tid >> 5] = contrib;
    __syncthreads();

    if (tid == 0) {
        float s = 0.0f;
#pragma unroll
        for (int w = 0; w < TPB / 32; ++w) s += warp_sums[w];
        g_partials[blockIdx.x] = s;
        __threadfence();
        unsigned int done = atomicAdd(&g_count, 1u);
        sh_last = (done == NBLOCKS - 1);
    }
    __syncthreads();
    if (!sh_last) return;

    // ---- fused final reduction in the last block (fixed order) ----
    __threadfence();
    float v = 0.0f;
#pragma unroll
    for (int j = 0; j < NBLOCKS / TPB; ++j)
        v += __ldcg(&g_partials[tid + TPB * j]);
#pragma unroll
    for (int off = 16; off > 0; off >>= 1)
        v += __shfl_down_sync(0xFFFFFFFFu, v, off);
    if ((tid & 31) == 0) warp_sums[tid >> 5] = v;
    __syncthreads();
    if (tid == 0) {
        float s = 0.0f;
#pragma unroll
        for (int w = 0; w < TPB / 32; ++w) s += warp_sums[w];
        out[0]  = s * (1.0f / (float)(BT * NPTS));
        g_count = 0u;                           // reset for next graph replay
    }
}

extern "C" void kernel_launch(void* const* d_in, const int* in_sizes, int n_in,
                              void* d_out, int out_size) {
    const float* x = (const float*)d_in[0];
    const float* y = (const float*)d_in[1];
    float* out = (float*)d_out;
    (void)in_sizes; (void)n_in; (void)out_size;

    chamfer_kernel<<<NBLOCKS, TPB>>>(x, y, out);
}

// round 7
// speedup vs baseline: 1.2297x; 1.2297x over previous
#include <cuda_runtime.h>
#include <math.h>

// Problem constants (B=2, T=16, N=1024, D=3)
#define BT       32
#define NPTS     1024
#define TPB      256
#define NQ       16                   // candidate lane-split groups
#define POWN     8                    // owned points per thread
#define OGRP     (TPB / NQ)           // 16 owned groups
#define OWNED    (OGRP * POWN)        // 128 owned points per block
#define OCH      (NPTS / OWNED)       // 8 owned chunks per (batch, direction)
#define CPAIRS   (NPTS / 2)           // 512 packed candidate pairs in smem
#define ITERS    (CPAIRS / NQ)        // 32 pair-iterations per thread
#define NBLOCKS  (BT * 2 * OCH)       // 512
#define EPS      1e-6f

__device__ float        g_partials[NBLOCKS];
__device__ unsigned int g_count = 0;

// ---- packed f32x2 helpers (sm_100+; ptxas never auto-fuses) ----
__device__ __forceinline__ unsigned long long pack2(float a, float b) {
    unsigned long long r;
    asm("mov.b64 %0, {%1, %2};" : "=l"(r) : "f"(a), "f"(b));
    return r;
}
__device__ __forceinline__ unsigned long long fma2(unsigned long long a,
                                                   unsigned long long b,
                                                   unsigned long long c) {
    unsigned long long d;
    asm("fma.rn.f32x2 %0, %1, %2, %3;" : "=l"(d) : "l"(a), "l"(b), "l"(c));
    return d;
}
__device__ __forceinline__ void unpack2(unsigned long long v, float& lo, float& hi) {
    asm("mov.b64 {%0, %1}, %2;" : "=f"(lo), "=f"(hi) : "l"(v));
}

__global__ void __launch_bounds__(TPB, 3)
chamfer_kernel(const float* __restrict__ x, const float* __restrict__ y,
               float* __restrict__ out) {
    // Candidate pairs: 32B = {x0,x1, y0,y1, z0,z1, -h0,-h1}; 512 pairs = 16KB
    __shared__ float s_c[CPAIRS * 8];
    __shared__ float s_own[OWNED * 3];          // raw owned coords (1.5KB)
    __shared__ float warp_sums[TPB / 32];
    __shared__ bool  sh_last;

    const int bt    = blockIdx.x >> 4;          // batch (32)
    const int dir   = (blockIdx.x >> 3) & 1;    // 0: owned=x, cand=y; 1: reverse
    const int chunk = blockIdx.x & 7;           // owned chunk (8)
    const int tid   = threadIdx.x;

    const float* xb = x + (size_t)bt * NPTS * 3;
    const float* yb = y + (size_t)bt * NPTS * 3;
    const float* ownp = dir ? yb : xb;
    const float* cndp = dir ? xb : yb;

    // ---- stage owned chunk raw via coalesced float4 (128 pts = 96 float4) ----
    if (tid < OWNED * 3 / 4) {
        const float4 v = ((const float4*)(ownp + (size_t)chunk * OWNED * 3))[tid];
        ((float4*)s_own)[tid] = v;
    }

    // ---- stage ALL 1024 candidates: 3 LDG.128 -> repack -> 2x2 STS.128 ----
    {
        // thread t handles pairs 2t, 2t+1 (points 4t..4t+3, floats 12t..12t+11)
        const float4* cf = (const float4*)cndp;
        float4 v0 = cf[3 * tid + 0];
        float4 v1 = cf[3 * tid + 1];
        float4 v2 = cf[3 * tid + 2];
        // pair 0: points (v0.x,v0.y,v0.z) and (v0.w,v1.x,v1.y)
        {
            float nh0 = -0.5f * (v0.x * v0.x + v0.y * v0.y + v0.z * v0.z);
            float nh1 = -0.5f * (v0.w * v0.w + v1.x * v1.x + v1.y * v1.y);
            float* dst = s_c + (2 * tid) * 8;
            ((float4*)dst)[0] = make_float4(v0.x, v0.w, v0.y, v1.x);
            ((float4*)dst)[1] = make_float4(v0.z, v1.y, nh0, nh1);
        }
        // pair 1: points (v1.z,v1.w,v2.x) and (v2.y,v2.z,v2.w)
        {
            float nh0 = -0.5f * (v1.z * v1.z + v1.w * v1.w + v2.x * v2.x);
            float nh1 = -0.5f * (v2.y * v2.y + v2.z * v2.z + v2.w * v2.w);
            float* dst = s_c + (2 * tid + 1) * 8;
            ((float4*)dst)[0] = make_float4(v1.z, v2.y, v1.w, v2.z);
            ((float4*)dst)[1] = make_float4(v2.x, v2.w, nh0, nh1);
        }
    }
    __syncthreads();

    // ---- owned register tile: 8 points from smem, splatted for f32x2 ----
    const int q = tid & (NQ - 1);               // candidate group 0..15
    const int g = tid >> 4;                     // owned group 0..15
    unsigned long long Ax2[POWN], Ay2[POWN], Az2[POWN];
    float h[POWN];
#pragma unroll
    for (int k = 0; k < POWN; ++k) {
        const int o = g + OGRP * k;             // local owned index
        float a0 = s_own[3 * o + 0], a1 = s_own[3 * o + 1], a2 = s_own[3 * o + 2];
        Ax2[k] = pack2(a0, a0);
        Ay2[k] = pack2(a1, a1);
        Az2[k] = pack2(a2, a2);
        h[k]   = 0.5f * (a0 * a0 + a1 * a1 + a2 * a2);
    }

    float mlo[POWN], mhi[POWN];
#pragma unroll
    for (int k = 0; k < POWN; ++k) { mlo[k] = -INFINITY; mhi[k] = -INFINITY; }

    // ---- hot loop: one 32B candidate-pair load feeds 8 owned points ----
    const ulonglong2* cp = (const ulonglong2*)s_c;
#pragma unroll 8
    for (int i = 0; i < ITERS; ++i) {
        const int pr = NQ * i + q;
        ulonglong2 va = cp[2 * pr];             // (x0,x1),(y0,y1)
        ulonglong2 vb = cp[2 * pr + 1];         // (z0,z1),(-h0,-h1)
#pragma unroll
        for (int k = 0; k < POWN; ++k) {
            unsigned long long t = fma2(Az2[k], vb.x, vb.y);
            t = fma2(Ay2[k], va.y, t);
            t = fma2(Ax2[k], va.x, t);
            float lo, hi;
            unpack2(t, lo, hi);
            mlo[k] = fmaxf(mlo[k], lo);
            mhi[k] = fmaxf(mhi[k], hi);
        }
    }

    // ---- combine the 16 candidate groups (within warp) ----
    float contrib = 0.0f;
#pragma unroll
    for (int k = 0; k < POWN; ++k) {
        float m = fmaxf(mlo[k], mhi[k]);
        m = fmaxf(m, __shfl_xor_sync(0xFFFFFFFFu, m, 1));
        m = fmaxf(m, __shfl_xor_sync(0xFFFFFFFFu, m, 2));
        m = fmaxf(m, __shfl_xor_sync(0xFFFFFFFFu, m, 4));
        m = fmaxf(m, __shfl_xor_sync(0xFFFFFFFFu, m, 8));
        // min_i sq = 2*(h - m); clamp, dist = sqrt(EPS + sq)
        float sq = fmaxf(2.0f * (h[k] - m), 0.0f);
        if (q == 0) contrib += sqrtf(EPS + sq);
    }

    // ---- block reduction (fixed order -> deterministic) ----
#pragma unroll
    for (int off = 16; off > 0; off >>= 1)
        contrib += __shfl_down_sync(0xFFFFFFFFu, contrib, off);
    if ((tid & 31) == 0) warp_sums[tid >> 5] = contrib;
    __syncthreads();

    if (tid == 0) {
        float s = 0.0f;
#pragma unroll
        for (int w = 0; w < TPB / 32; ++w) s += warp_sums[w];
        g_partials[blockIdx.x] = s;
        __threadfence();
        unsigned int done = atomicAdd(&g_count, 1u);
        sh_last = (done == NBLOCKS - 1);
    }
    __syncthreads();
    if (!sh_last) return;

    // ---- fused final reduction in the last block (fixed order) ----
    __threadfence();
    float v = __ldcg(&g_partials[tid]) + __ldcg(&g_partials[tid + TPB]);
#pragma unroll
    for (int off = 16; off > 0; off >>= 1)
        v += __shfl_down_sync(0xFFFFFFFFu, v, off);
    if ((tid & 31) == 0) warp_sums[tid >> 5] = v;
    __syncthreads();
    if (tid == 0) {
        float s = 0.0f;
#pragma unroll
        for (int w = 0; w < TPB / 32; ++w) s += warp_sums[w];
        out[0]  = s * (1.0f / (float)(BT * NPTS));
        g_count = 0u;                           // reset for next graph replay
    }
}

extern "C" void kernel_launch(void* const* d_in, const int* in_sizes, int n_in,
                              void* d_out, int out_size) {
    const float* x = (const float*)d_in[0];
    const float* y = (const float*)d_in[1];
    float* out = (float*)d_out;
    (void)in_sizes; (void)n_in; (void)out_size;

    chamfer_kernel<<<NBLOCKS, TPB>>>(x, y, out);
}

// round 8
// speedup vs baseline: 1.3788x; 1.1212x over previous
#include <cuda_runtime.h>
#include <math.h>

// Problem constants (B=2, T=16, N=1024, D=3)
#define BT       32
#define NPTS     1024
#define TPB      256
#define NQ       16                   // candidate lane-split groups
#define POWN     8                    // owned points per thread
#define OGRP     (TPB / NQ)           // 16 owned groups
#define OWNED    (OGRP * POWN)        // 128 owned points per block
#define OCH      (NPTS / OWNED)       // 8 owned chunks per (batch, direction)
#define CPAIRS   (NPTS / 2)           // 512 packed candidate pairs in smem
#define ITERS    (CPAIRS / NQ)        // 32 pair-iterations per thread
#define NBLOCKS  (BT * 2 * OCH)       // 512
#define EPS      1e-6f

__device__ float        g_partials[NBLOCKS];
__device__ unsigned int g_count = 0;

// ---- packed f32x2 helpers (sm_100+; ptxas never auto-fuses) ----
__device__ __forceinline__ unsigned long long pack2(float a, float b) {
    unsigned long long r;
    asm("mov.b64 %0, {%1, %2};" : "=l"(r) : "f"(a), "f"(b));
    return r;
}
__device__ __forceinline__ unsigned long long fma2(unsigned long long a,
                                                   unsigned long long b,
                                                   unsigned long long c) {
    unsigned long long d;
    asm("fma.rn.f32x2 %0, %1, %2, %3;" : "=l"(d) : "l"(a), "l"(b), "l"(c));
    return d;
}
__device__ __forceinline__ void unpack2(unsigned long long v, float& lo, float& hi) {
    asm("mov.b64 {%0, %1}, %2;" : "=f"(lo), "=f"(hi) : "l"(v));
}

__global__ void __launch_bounds__(TPB, 3)
chamfer_kernel(const float* __restrict__ x, const float* __restrict__ y,
               float* __restrict__ out) {
    // Split candidate layout (conflict-free 16B lane stride):
    //   s_ca[p] = {x0, x1, y0, y1}   s_cb[p] = {z0, z1, -h0, -h1}
    __shared__ float4 s_ca[CPAIRS];             // 8KB
    __shared__ float4 s_cb[CPAIRS];             // 8KB
    __shared__ float  s_own[OWNED * 3];         // raw owned coords (1.5KB)
    __shared__ float  warp_sums[TPB / 32];
    __shared__ bool   sh_last;

    const int bt    = blockIdx.x >> 4;          // batch (32)
    const int dir   = (blockIdx.x >> 3) & 1;    // 0: owned=x, cand=y; 1: reverse
    const int chunk = blockIdx.x & 7;           // owned chunk (8)
    const int tid   = threadIdx.x;

    const float* xb = x + (size_t)bt * NPTS * 3;
    const float* yb = y + (size_t)bt * NPTS * 3;
    const float* ownp = dir ? yb : xb;
    const float* cndp = dir ? xb : yb;

    // ---- stage owned chunk raw via coalesced float4 (128 pts = 96 float4) ----
    if (tid < OWNED * 3 / 4) {
        const float4 v = ((const float4*)(ownp + (size_t)chunk * OWNED * 3))[tid];
        ((float4*)s_own)[tid] = v;
    }

    // ---- stage ALL 1024 candidates: 3 LDG.128 -> repack -> 4 STS.128 ----
    {
        // thread t handles pairs 2t, 2t+1 (points 4t..4t+3)
        const float4* cf = (const float4*)cndp;
        float4 v0 = cf[3 * tid + 0];
        float4 v1 = cf[3 * tid + 1];
        float4 v2 = cf[3 * tid + 2];
        // pair 0: points (v0.x,v0.y,v0.z) and (v0.w,v1.x,v1.y)
        {
            float nh0 = -0.5f * (v0.x * v0.x + v0.y * v0.y + v0.z * v0.z);
            float nh1 = -0.5f * (v0.w * v0.w + v1.x * v1.x + v1.y * v1.y);
            s_ca[2 * tid] = make_float4(v0.x, v0.w, v0.y, v1.x);
            s_cb[2 * tid] = make_float4(v0.z, v1.y, nh0, nh1);
        }
        // pair 1: points (v1.z,v1.w,v2.x) and (v2.y,v2.z,v2.w)
        {
            float nh0 = -0.5f * (v1.z * v1.z + v1.w * v1.w + v2.x * v2.x);
            float nh1 = -0.5f * (v2.y * v2.y + v2.z * v2.z + v2.w * v2.w);
            s_ca[2 * tid + 1] = make_float4(v1.z, v2.y, v1.w, v2.z);
            s_cb[2 * tid + 1] = make_float4(v2.x, v2.w, nh0, nh1);
        }
    }
    __syncthreads();

    // ---- owned register tile: 8 points from smem, splatted for f32x2 ----
    const int q = tid & (NQ - 1);               // candidate group 0..15
    const int g = tid >> 4;                     // owned group 0..15
    unsigned long long Ax2[POWN], Ay2[POWN], Az2[POWN];
#pragma unroll
    for (int k = 0; k < POWN; ++k) {
        const int o = g + OGRP * k;             // local owned index
        float a0 = s_own[3 * o + 0], a1 = s_own[3 * o + 1], a2 = s_own[3 * o + 2];
        Ax2[k] = pack2(a0, a0);
        Ay2[k] = pack2(a1, a1);
        Az2[k] = pack2(a2, a2);
    }

    float m[POWN];
#pragma unroll
    for (int k = 0; k < POWN; ++k) m[k] = -INFINITY;

    // ---- hot loop: 2x LDS.128 (16B lane stride, conflict-free) per pair ----
    const ulonglong2* pa = (const ulonglong2*)s_ca + q;
    const ulonglong2* pb = (const ulonglong2*)s_cb + q;
#pragma unroll 8
    for (int i = 0; i < ITERS; ++i) {
        ulonglong2 va = pa[NQ * i];             // (x0,x1),(y0,y1)
        ulonglong2 vb = pb[NQ * i];             // (z0,z1),(-h0,-h1)
#pragma unroll
        for (int k = 0; k < POWN; ++k) {
            unsigned long long t = fma2(Az2[k], vb.x, vb.y);
            t = fma2(Ay2[k], va.y, t);
            t = fma2(Ax2[k], va.x, t);
            float lo, hi;
            unpack2(t, lo, hi);
            m[k] = fmaxf(m[k], fmaxf(lo, hi));  // merged tree, 1 accumulator
        }
    }

    // ---- combine the 16 candidate groups (within warp), epilogue h from smem ----
    float contrib = 0.0f;
#pragma unroll
    for (int k = 0; k < POWN; ++k) {
        float mm = m[k];
        mm = fmaxf(mm, __shfl_xor_sync(0xFFFFFFFFu, mm, 1));
        mm = fmaxf(mm, __shfl_xor_sync(0xFFFFFFFFu, mm, 2));
        mm = fmaxf(mm, __shfl_xor_sync(0xFFFFFFFFu, mm, 4));
        mm = fmaxf(mm, __shfl_xor_sync(0xFFFFFFFFu, mm, 8));
        if (q == 0) {
            const int o = g + OGRP * k;
            float a0 = s_own[3 * o + 0], a1 = s_own[3 * o + 1], a2 = s_own[3 * o + 2];
            float h = 0.5f * (a0 * a0 + a1 * a1 + a2 * a2);
            // min_i sq = 2*(h - mm); clamp, dist = sqrt(EPS + sq)
            float sq = fmaxf(2.0f * (h - mm), 0.0f);
            contrib += sqrtf(EPS + sq);
        }
    }

    // ---- block reduction (fixed order -> deterministic) ----
#pragma unroll
    for (int off = 16; off > 0; off >>= 1)
        contrib += __shfl_down_sync(0xFFFFFFFFu, contrib, off);
    if ((tid & 31) == 0) warp_sums[tid >> 5] = contrib;
    __syncthreads();

    if (tid == 0) {
        float s = 0.0f;
#pragma unroll
        for (int w = 0; w < TPB / 32; ++w) s += warp_sums[w];
        g_partials[blockIdx.x] = s;
        __threadfence();
        unsigned int done = atomicAdd(&g_count, 1u);
        sh_last = (done == NBLOCKS - 1);
    }
    __syncthreads();
    if (!sh_last) return;

    // ---- fused final reduction in the last block (fixed order) ----
    __threadfence();
    float v = __ldcg(&g_partials[tid]) + __ldcg(&g_partials[tid + TPB]);
#pragma unroll
    for (int off = 16; off > 0; off >>= 1)
        v += __shfl_down_sync(0xFFFFFFFFu, v, off);
    if ((tid & 31) == 0) warp_sums[tid >> 5] = v;
    __syncthreads();
    if (tid == 0) {
        float s = 0.0f;
#pragma unroll
        for (int w = 0; w < TPB / 32; ++w) s += warp_sums[w];
        out[0]  = s * (1.0f / (float)(BT * NPTS));
        g_count = 0u;                           // reset for next graph replay
    }
}

extern "C" void kernel_launch(void* const* d_in, const int* in_sizes, int n_in,
                              void* d_out, int out_size) {
    const float* x = (const float*)d_in[0];
    const float* y = (const float*)d_in[1];
    float* out = (float*)d_out;
    (void)in_sizes; (void)n_in; (void)out_size;

    chamfer_kernel<<<NBLOCKS, TPB>>>(x, y, out);
}